// round 14
// baseline (speedup 1.0000x reference)
#include <cuda_runtime.h>
#include <math.h>
#include <stdint.h>

#define BATCH 2
#define SEQ   4096
#define CHN   1280
#define HEADS 8
#define HDIM  160
#define BHN   16          // BATCH*HEADS
#define MTOT  8192        // BATCH*SEQ

// Scratch (allocation-free rule: __device__ globals)
__device__ float g_q [(size_t)BHN * SEQ * HDIM];   // [bh][s][d] tf32, pre-scaled
__device__ float g_kT[(size_t)BHN * HDIM * SEQ];   // [bh][d/8][s][8] pair-interleaved
__device__ float g_vT[(size_t)BHN * HDIM * SEQ];   // [bh][d][s/8][8] pair-interleaved
__device__ float g_ao[(size_t)MTOT * CHN];         // [row][col'] col-permuted tf32
__device__ float g_x [(size_t)MTOT * CHN];         // [row][col'] col-permuted tf32
__device__ float g_wq[(size_t)CHN * CHN];          // [k/8][n][8] pair-interleaved
__device__ float g_wk[(size_t)CHN * CHN];
__device__ float g_wv[(size_t)CHN * CHN];
__device__ float g_wo[(size_t)CHN * CHN];

// ---------------------------------------------------------------------------
// helpers
// ---------------------------------------------------------------------------
__device__ __forceinline__ unsigned f2tf(float x) {
    unsigned r;
    asm("cvt.rna.tf32.f32 %0, %1;" : "=r"(r) : "f"(x));
    return r;
}
__device__ __forceinline__ float uaf(unsigned u) { return __uint_as_float(u); }
__device__ __forceinline__ int perm8(int kk) { return ((kk & 3) << 1) | (kk >> 2); }

__device__ __forceinline__ void mma8(float* c, const unsigned* a, const unsigned* b) {
    asm volatile(
        "mma.sync.aligned.m16n8k8.row.col.f32.tf32.tf32.f32 "
        "{%0,%1,%2,%3}, {%4,%5,%6,%7}, {%8,%9}, {%0,%1,%2,%3};\n"
        : "+f"(c[0]), "+f"(c[1]), "+f"(c[2]), "+f"(c[3])
        : "r"(a[0]), "r"(a[1]), "r"(a[2]), "r"(a[3]), "r"(b[0]), "r"(b[1]));
}
// a-pair fragments as float2: lo = k=t, hi = k=t+4
__device__ __forceinline__ void mma8p(float* c, float2 a0, float2 a1, float2 b) {
    unsigned af[4] = { __float_as_uint(a0.x), __float_as_uint(a1.x),
                       __float_as_uint(a0.y), __float_as_uint(a1.y) };
    unsigned bf[2] = { __float_as_uint(b.x), __float_as_uint(b.y) };
    mma8(c, af, bf);
}

__device__ __forceinline__ void cp16(uint32_t dst, const float* src) {
    asm volatile("cp.async.cg.shared.global [%0], [%1], 16;\n"
                 :: "r"(dst), "l"(src));
}
__device__ __forceinline__ void cp_commit() {
    asm volatile("cp.async.commit_group;\n");
}
__device__ __forceinline__ void cp_wait0() {
    asm volatile("cp.async.wait_group 0;\n" ::: "memory");
}

// exp(x) for x <= 0 on the FMA pipe (no MUFU). |rel err| ~ 2.4e-6.
__device__ __forceinline__ float fast_exp(float x) {
    x = fmaxf(x, -80.0f);
    float y = x * 1.4426950408889634f;
    float t = y + 12582912.0f;
    int   e = __float_as_int(t);
    float n = t - 12582912.0f;
    float f = y - n;
    float p = 1.3333558e-3f;
    p = fmaf(p, f, 9.6181291e-3f);
    p = fmaf(p, f, 5.5504109e-2f);
    p = fmaf(p, f, 2.4022651e-1f);
    p = fmaf(p, f, 6.9314718e-1f);
    p = fmaf(p, f, 1.0f);
    return __int_as_float(__float_as_int(p) + (e << 23));
}

// ---------------------------------------------------------------------------
// Kernel 0: round X + weights to tf32, writing mma-friendly layouts.
// X/g_ao-style: column c -> (c & ~7) + perm8(c & 7)
// W: [k][n] -> g_w2[(k>>3)*(CHN*8) + n*8 + perm8(k&7)]
// ---------------------------------------------------------------------------
__global__ __launch_bounds__(256) void cvt_all(
    const float* __restrict__ X,  const float* __restrict__ Wq,
    const float* __restrict__ Wk, const float* __restrict__ Wv,
    const float* __restrict__ Wo)
{
    const int NX = MTOT * CHN / 4;
    const int NW = CHN * CHN / 4;
    int i = blockIdx.x * 256 + threadIdx.x;
    if (i < NX) {
        int base = i * 4;
        int row = base / CHN, c = base - row * CHN;
        float4 v = *(const float4*)&X[(size_t)row * CHN + c];
        float* d = &g_x[(size_t)row * CHN + (c & ~7) + ((c >> 2) & 1)];
        d[0] = uaf(f2tf(v.x)); d[2] = uaf(f2tf(v.y));
        d[4] = uaf(f2tf(v.z)); d[6] = uaf(f2tf(v.w));
        return;
    }
    i -= NX;
    if (i >= 4 * NW) return;
    const float* s; float* d2;
    if (i < NW)          { s = Wq; d2 = g_wq; }
    else if (i < 2 * NW) { s = Wk; d2 = g_wk; i -= NW; }
    else if (i < 3 * NW) { s = Wv; d2 = g_wv; i -= 2 * NW; }
    else                 { s = Wo; d2 = g_wo; i -= 3 * NW; }
    int base = i * 4;
    int k = base / CHN, n = base - k * CHN;
    float4 v = *(const float4*)&s[(size_t)k * CHN + n];
    float* d = &d2[(size_t)(k >> 3) * (CHN * 8) + (size_t)n * 8 + perm8(k & 7)];
    d[0] = uaf(f2tf(v.x)); d[8] = uaf(f2tf(v.y));
    d[16] = uaf(f2tf(v.z)); d[24] = uaf(f2tf(v.w));
}

// ---------------------------------------------------------------------------
// GEMM core: cp.async double-buffered; A col-permuted, B in w2 layout.
// warp layout 2(m) x 4(n); warp tile 64x32 -> c[16][4]
// ---------------------------------------------------------------------------
#define ASTR 40
#define ABUF (128 * ASTR)   // 5120 floats
#define BBUF (32 * 128)     // 4096 floats: [ks(4)][n(128)][8]
#define GEMM_SMEM ((2 * (ABUF + BBUF)) * 4)   // 73728 bytes

__device__ __forceinline__ void gemm_core(
    const float* __restrict__ A, const float* __restrict__ B2,
    int row0, int col0, float c[16][4], float* sm)
{
    float* As = sm;
    float* Bs = sm + 2 * ABUF;
    uint32_t As_u = (uint32_t)__cvta_generic_to_shared(As);
    uint32_t Bs_u = (uint32_t)__cvta_generic_to_shared(Bs);

    const int tid = threadIdx.x;
    const int warp = tid >> 5, lane = tid & 31;
    const int g = lane >> 2, t = lane & 3;
    const int wm = warp >> 2, wn = warp & 3;

    auto issue = [&](int kb, int buf) {
        int kblk0 = kb >> 3;
#pragma unroll
        for (int it = 0; it < 4; it++) {
            int lin = it * 256 + tid;
            int ra = lin >> 3, ca = (lin & 7) << 2;
            cp16(As_u + (uint32_t)(buf * ABUF + ra * ASTR + ca) * 4,
                 &A[(size_t)(row0 + ra) * CHN + kb + ca]);
            int ks = lin >> 8, nn = (lin >> 1) & 127, p4 = (lin & 1) << 2;
            cp16(Bs_u + (uint32_t)(buf * BBUF + lin * 4) * 4,
                 &B2[(size_t)(kblk0 + ks) * (CHN * 8) + (size_t)(col0 + nn) * 8 + p4]);
        }
        cp_commit();
    };

    issue(0, 0);

    int buf = 0;
    for (int kb = 0; kb < CHN; kb += 32, buf ^= 1) {
        cp_wait0();
        __syncthreads();
        if (kb + 32 < CHN) issue(kb + 32, buf ^ 1);
        const float* Ab = As + buf * ABUF;
        const float* Bb = Bs + buf * BBUF;
#pragma unroll
        for (int ks = 0; ks < 4; ks++) {
            float2 a0[4], a1[4], bfr[4];
#pragma unroll
            for (int mt = 0; mt < 4; mt++) {
                int r = wm * 64 + mt * 16 + g;
                a0[mt] = *(const float2*)&Ab[r * ASTR + ks * 8 + 2 * t];
                a1[mt] = *(const float2*)&Ab[(r + 8) * ASTR + ks * 8 + 2 * t];
            }
#pragma unroll
            for (int nt = 0; nt < 4; nt++) {
                int cc = wn * 32 + nt * 8 + g;
                bfr[nt] = *(const float2*)&Bb[ks * 1024 + cc * 8 + 2 * t];
            }
#pragma unroll
            for (int mt = 0; mt < 4; mt++)
#pragma unroll
                for (int nt = 0; nt < 4; nt++)
                    mma8p(c[mt * 4 + nt], a0[mt], a1[mt], bfr[nt]);
        }
        __syncthreads();
    }
}

// ---------------------------------------------------------------------------
// Kernel 1: fused QKV projection. Epilogues write attention-ready layouts.
// ---------------------------------------------------------------------------
__global__ __launch_bounds__(256, 2) void qkv_gemm()
{
    extern __shared__ float sm[];
    float c[16][4];
#pragma unroll
    for (int i = 0; i < 16; i++)
#pragma unroll
        for (int j = 0; j < 4; j++) c[i][j] = 0.f;

    const float* __restrict__ W =
        (blockIdx.z == 0) ? g_wq : (blockIdx.z == 1 ? g_wk : g_wv);
    gemm_core(g_x, W, blockIdx.y * 128, blockIdx.x * 128, c, sm);

    const int lane = threadIdx.x & 31, warp = threadIdx.x >> 5;
    const int g = lane >> 2, t = lane & 3;
    const int wm = warp >> 2, wn = warp & 3;
    const float scale = 0.07905694150420949f;  // 1/sqrt(160)

#pragma unroll
    for (int mt = 0; mt < 4; mt++) {
#pragma unroll
        for (int nt = 0; nt < 4; nt++) {
            int rowb = blockIdx.y * 128 + wm * 64 + mt * 16 + g;
            int col  = blockIdx.x * 128 + wn * 32 + nt * 8 + 2 * t;
            if (blockIdx.z == 0) {
#pragma unroll
                for (int half = 0; half < 2; half++) {
                    int row = rowb + half * 8;
                    int b = row >> 12, s = row & (SEQ - 1);
                    int h = col / HDIM, d = col - h * HDIM;
                    float2 v = make_float2(
                        uaf(f2tf(c[mt * 4 + nt][half * 2] * scale)),
                        uaf(f2tf(c[mt * 4 + nt][half * 2 + 1] * scale)));
                    *(float2*)&g_q[((size_t)(b * HEADS + h) * SEQ + s) * HDIM + d] = v;
                }
            } else if (blockIdx.z == 1) {
                // K: [bh][d>>3][s][8], inner perm8(d&7)
#pragma unroll
                for (int i = 0; i < 4; i++) {
                    int row = rowb + (i >> 1) * 8;
                    int cj  = col + (i & 1);
                    int b = row >> 12, s = row & (SEQ - 1);
                    int h = cj / HDIM, d = cj - h * HDIM;
                    int bh = b * HEADS + h;
                    g_kT[(((size_t)(bh * 20 + (d >> 3))) * SEQ + s) * 8 + perm8(d & 7)] =
                        uaf(f2tf(c[mt * 4 + nt][i]));
                }
            } else {
                // V: [bh][d][s>>3][8], inner perm8(s&7)
#pragma unroll
                for (int i = 0; i < 4; i++) {
                    int row = rowb + (i >> 1) * 8;
                    int cj  = col + (i & 1);
                    int b = row >> 12, s = row & (SEQ - 1);
                    int h = cj / HDIM, d = cj - h * HDIM;
                    int bh = b * HEADS + h;
                    g_vT[(((size_t)(bh * HDIM + d)) * 512 + (s >> 3)) * 8 + perm8(s & 7)] =
                        uaf(f2tf(c[mt * 4 + nt][i]));
                }
            }
        }
    }
}

// ---------------------------------------------------------------------------
// Kernel 2: flash attention. Q in regs; pair-interleaved K/V/P, LDS.64 frags.
// Warp layout: 4(m) x 2(n). S: warp 16x32. PV: warp 16x80.
// ---------------------------------------------------------------------------
#define KBUF 10240          // [ks(20)][key(64)][8]
#define VSTRD 72            // [d(160)][ksb(8)*8 + pad]
#define VBUF (HDIM * VSTRD) // 11520
#define PSTRD 72
#define PBUF (64 * PSTRD)   // 4608
#define QSTR 164
// floats: sK[2*KBUF] | sV[2*VBUF] | sP | sMx[128] | sSm[128]
#define ATTN_SMEM ((2 * KBUF + 2 * VBUF + PBUF + 256) * 4)   // 193536 B

__global__ __launch_bounds__(256, 1) void attn_kernel()
{
    extern __shared__ float smem[];
    float* sK  = smem;
    float* sV  = smem + 2 * KBUF;
    float* sP  = sV + 2 * VBUF;
    float* sMx = sP + PBUF;
    float* sSm = sMx + 128;
    uint32_t smem_u = (uint32_t)__cvta_generic_to_shared(smem);

    const int bh = blockIdx.y;
    const int q0 = blockIdx.x * 64;
    const int tid = threadIdx.x, warp = tid >> 5, lane = tid & 31;
    const int g = lane >> 2, t = lane & 3;
    const int wm = warp >> 1, wn = warp & 1;
    const int r0 = wm * 16 + g, r1 = r0 + 8;

    // ---- stage Q (tf32, pre-scaled) through smem, frags -> regs ----
    const float* __restrict__ Qg = g_q + ((size_t)bh * SEQ + q0) * HDIM;
#pragma unroll
    for (int it = 0; it < 10; it++) {
        int lin = it * 256 + tid;            // 2560 float4
        int r = lin / 40, c4 = (lin % 40) * 4;
        *(float4*)&smem[r * QSTR + c4] = *(const float4*)&Qg[(size_t)r * HDIM + c4];
    }
    __syncthreads();
    unsigned qf[20][4];
#pragma unroll
    for (int ks = 0; ks < 20; ks++) {
        qf[ks][0] = __float_as_uint(smem[r0 * QSTR + ks * 8 + t]);
        qf[ks][1] = __float_as_uint(smem[r1 * QSTR + ks * 8 + t]);
        qf[ks][2] = __float_as_uint(smem[r0 * QSTR + ks * 8 + t + 4]);
        qf[ks][3] = __float_as_uint(smem[r1 * QSTR + ks * 8 + t + 4]);
    }
    __syncthreads();

    const float* __restrict__ Kg = g_kT + (size_t)bh * HDIM * SEQ;  // [dblk][s][8]
    const float* __restrict__ Vg = g_vT + (size_t)bh * HDIM * SEQ;  // [d][sblk][8]

    auto issue_tile = [&](int kt, int buf) {
#pragma unroll
        for (int it = 0; it < 10; it++) {
            int lin = it * 256 + tid;
            // K: [dblk][key][8] contiguous both sides
            int dblk = lin >> 7, rem = lin & 127;
            int key = rem >> 1, p4 = (lin & 1) << 2;
            cp16(smem_u + (uint32_t)(buf * KBUF + lin * 4) * 4,
                 &Kg[(size_t)dblk * (SEQ * 8) + (size_t)(kt + key) * 8 + p4]);
            // V: per-d array is 4096 floats ([sblk(512)][8]); tile kt spans
            // [kt, kt+64) contiguous floats within it.
            int d = lin >> 4, c4 = (lin & 15) << 2;
            cp16(smem_u + (uint32_t)(2 * KBUF + buf * VBUF + d * VSTRD + c4) * 4,
                 &Vg[(size_t)d * 4096 + kt + c4]);
        }
        cp_commit();
    };
    issue_tile(0, 0);

    float o[10][4];
#pragma unroll
    for (int u = 0; u < 10; u++)
#pragma unroll
        for (int j = 0; j < 4; j++) o[u][j] = 0.f;
    float m0v = -1e30f, m1v = -1e30f, l0 = 0.f, l1 = 0.f;

    // perm positions for P stores: key kk=2t -> pp0, kk=2t+1 -> pp0+2
    const int pp0 = ((2 * t) & 3) * 2 + (t >> 1);

    for (int idx = 0; idx < 64; idx++) {
        const int buf = idx & 1;
        cp_wait0();
        __syncthreads();                       // tile ready + prev PV done
        if (idx + 1 < 64) issue_tile((idx + 1) * 64, buf ^ 1);
        const float* Kb = sK + buf * KBUF;
        const float* Vb = sV + buf * VBUF;

        // ---- S = Q @ K^T ----
        float s[4][4];
#pragma unroll
        for (int nt = 0; nt < 4; nt++)
#pragma unroll
            for (int j = 0; j < 4; j++) s[nt][j] = 0.f;

#pragma unroll
        for (int ks = 0; ks < 20; ks++) {
#pragma unroll
            for (int nt = 0; nt < 4; nt++) {
                int cc = wn * 32 + nt * 8 + g;
                float2 b = *(const float2*)&Kb[ks * 512 + cc * 8 + 2 * t];
                unsigned bf[2] = { __float_as_uint(b.x), __float_as_uint(b.y) };
                mma8(s[nt], qf[ks], bf);
            }
        }

        // ---- online softmax ----
        float mx0 = fmaxf(fmaxf(s[0][0], s[0][1]), fmaxf(s[1][0], s[1][1]));
        mx0 = fmaxf(mx0, fmaxf(fmaxf(s[2][0], s[2][1]), fmaxf(s[3][0], s[3][1])));
        float mx1 = fmaxf(fmaxf(s[0][2], s[0][3]), fmaxf(s[1][2], s[1][3]));
        mx1 = fmaxf(mx1, fmaxf(fmaxf(s[2][2], s[2][3]), fmaxf(s[3][2], s[3][3])));
        mx0 = fmaxf(mx0, __shfl_xor_sync(0xffffffffu, mx0, 1));
        mx0 = fmaxf(mx0, __shfl_xor_sync(0xffffffffu, mx0, 2));
        mx1 = fmaxf(mx1, __shfl_xor_sync(0xffffffffu, mx1, 1));
        mx1 = fmaxf(mx1, __shfl_xor_sync(0xffffffffu, mx1, 2));
        if (t == 0) { sMx[r0 * 2 + wn] = mx0; sMx[r1 * 2 + wn] = mx1; }
        __syncthreads();

        float mn0 = fmaxf(m0v, fmaxf(sMx[r0 * 2], sMx[r0 * 2 + 1]));
        float mn1 = fmaxf(m1v, fmaxf(sMx[r1 * 2], sMx[r1 * 2 + 1]));
        float a0 = fast_exp(m0v - mn0), a1 = fast_exp(m1v - mn1);
        m0v = mn0; m1v = mn1;

        float sum0 = 0.f, sum1 = 0.f;
#pragma unroll
        for (int nt = 0; nt < 4; nt++) {
            float p00 = fast_exp(s[nt][0] - mn0), p01 = fast_exp(s[nt][1] - mn0);
            float p10 = fast_exp(s[nt][2] - mn1), p11 = fast_exp(s[nt][3] - mn1);
            sum0 += p00 + p01; sum1 += p10 + p11;
            int kb8 = (wn * 4 + nt) * 8;       // key-block base in P layout
            sP[r0 * PSTRD + kb8 + pp0]     = uaf(f2tf(p00));
            sP[r0 * PSTRD + kb8 + pp0 + 2] = uaf(f2tf(p01));
            sP[r1 * PSTRD + kb8 + pp0]     = uaf(f2tf(p10));
            sP[r1 * PSTRD + kb8 + pp0 + 2] = uaf(f2tf(p11));
        }
        sum0 += __shfl_xor_sync(0xffffffffu, sum0, 1);
        sum0 += __shfl_xor_sync(0xffffffffu, sum0, 2);
        sum1 += __shfl_xor_sync(0xffffffffu, sum1, 1);
        sum1 += __shfl_xor_sync(0xffffffffu, sum1, 2);
        if (t == 0) { sSm[r0 * 2 + wn] = sum0; sSm[r1 * 2 + wn] = sum1; }
        __syncthreads();

        l0 = l0 * a0 + sSm[r0 * 2] + sSm[r0 * 2 + 1];
        l1 = l1 * a1 + sSm[r1 * 2] + sSm[r1 * 2 + 1];
#pragma unroll
        for (int u = 0; u < 10; u++) {
            o[u][0] *= a0; o[u][1] *= a0;
            o[u][2] *= a1; o[u][3] *= a1;
        }

        // ---- O += P @ V ----
#pragma unroll
        for (int ks = 0; ks < 8; ks++) {
            float2 pa0 = *(const float2*)&sP[r0 * PSTRD + ks * 8 + 2 * t];
            float2 pa1 = *(const float2*)&sP[r1 * PSTRD + ks * 8 + 2 * t];
#pragma unroll
            for (int u = 0; u < 10; u++) {
                int dc = wn * 80 + u * 8 + g;
                float2 b = *(const float2*)&Vb[dc * VSTRD + ks * 8 + 2 * t];
                mma8p(o[u], pa0, pa1, b);
            }
        }
    }

    // epilogue: write g_ao with column-permuted layout (for out_gemm A)
    const int b = bh >> 3, h = bh & 7;
    float inv0 = 1.0f / l0, inv1 = 1.0f / l1;
#pragma unroll
    for (int u = 0; u < 10; u++) {
        int cb = h * HDIM + wn * 80 + u * 8;       // 8-aligned block base
        size_t ro0 = (size_t)(b * SEQ + q0 + r0) * CHN + cb;
        size_t ro1 = (size_t)(b * SEQ + q0 + r1) * CHN + cb;
        g_ao[ro0 + pp0]     = uaf(f2tf(o[u][0] * inv0));
        g_ao[ro0 + pp0 + 2] = uaf(f2tf(o[u][1] * inv0));
        g_ao[ro1 + pp0]     = uaf(f2tf(o[u][2] * inv1));
        g_ao[ro1 + pp0 + 2] = uaf(f2tf(o[u][3] * inv1));
    }
}

// ---------------------------------------------------------------------------
// Kernel 3: output projection + bias
// ---------------------------------------------------------------------------
__global__ __launch_bounds__(256, 2) void out_gemm(
    const float* __restrict__ bias, float* __restrict__ out)
{
    extern __shared__ float sm[];
    float c[16][4];
#pragma unroll
    for (int i = 0; i < 16; i++)
#pragma unroll
        for (int j = 0; j < 4; j++) c[i][j] = 0.f;

    gemm_core(g_ao, g_wo, blockIdx.y * 128, blockIdx.x * 128, c, sm);

    const int lane = threadIdx.x & 31, warp = threadIdx.x >> 5;
    const int g = lane >> 2, t = lane & 3;
    const int wm = warp >> 2, wn = warp & 3;

#pragma unroll
    for (int mt = 0; mt < 4; mt++) {
#pragma unroll
        for (int nt = 0; nt < 4; nt++) {
            int rowb = blockIdx.y * 128 + wm * 64 + mt * 16 + g;
            int col  = blockIdx.x * 128 + wn * 32 + nt * 8 + 2 * t;
            float2 bv = *(const float2*)&bias[col];
#pragma unroll
            for (int half = 0; half < 2; half++) {
                int row = rowb + half * 8;
                float2 v = make_float2(c[mt * 4 + nt][half * 2] + bv.x,
                                       c[mt * 4 + nt][half * 2 + 1] + bv.y);
                *(float2*)&out[(size_t)row * CHN + col] = v;
            }
        }
    }
}

// ---------------------------------------------------------------------------
extern "C" void kernel_launch(void* const* d_in, const int* in_sizes, int n_in,
                              void* d_out, int out_size)
{
    const float* X    = (const float*)d_in[0];
    const float* Wq   = (const float*)d_in[1];
    const float* Wk   = (const float*)d_in[2];
    const float* Wv   = (const float*)d_in[3];
    const float* Wout = (const float*)d_in[4];
    const float* bout = (const float*)d_in[5];
    float* out = (float*)d_out;

    const int NX = MTOT * CHN / 4, NW = CHN * CHN / 4;
    cvt_all<<<(NX + 4 * NW + 255) / 256, 256>>>(X, Wq, Wk, Wv, Wout);

    cudaFuncSetAttribute(qkv_gemm,
                         cudaFuncAttributeMaxDynamicSharedMemorySize, GEMM_SMEM);
    qkv_gemm<<<dim3(CHN / 128, MTOT / 128, 3), 256, GEMM_SMEM>>>();

    cudaFuncSetAttribute(attn_kernel,
                         cudaFuncAttributeMaxDynamicSharedMemorySize, ATTN_SMEM);
    attn_kernel<<<dim3(SEQ / 64, BHN), 256, ATTN_SMEM>>>();

    cudaFuncSetAttribute(out_gemm,
                         cudaFuncAttributeMaxDynamicSharedMemorySize, GEMM_SMEM);
    out_gemm<<<dim3(CHN / 128, MTOT / 128), 256, GEMM_SMEM>>>(bout, out);
}

// round 16
// speedup vs baseline: 2.3961x; 2.3961x over previous
#include <cuda_runtime.h>
#include <cuda_fp16.h>
#include <math.h>
#include <stdint.h>

#define BATCH 2
#define SEQ   4096
#define CHN   1280
#define HEADS 8
#define HDIM  160
#define BHN   16
#define MTOT  8192

// Scratch (allocation-free rule: __device__ globals), all fp16 operands
__device__ __half g_xh [(size_t)MTOT * CHN];     // [row][k]
__device__ __half g_aoh[(size_t)MTOT * CHN];     // [row][k]
__device__ __half g_wqh[(size_t)CHN * CHN];      // W^T: [n][k]
__device__ __half g_wkh[(size_t)CHN * CHN];
__device__ __half g_wvh[(size_t)CHN * CHN];
__device__ __half g_woh[(size_t)CHN * CHN];
__device__ __half g_qh [(size_t)BHN * SEQ * HDIM]; // [bh][s][d], pre-scaled
__device__ __half g_kh [(size_t)BHN * SEQ * HDIM]; // [bh][s][d]
__device__ __half g_vh [(size_t)BHN * HDIM * SEQ]; // [bh][d][s] (transposed)

// ---------------------------------------------------------------------------
// helpers
// ---------------------------------------------------------------------------
__device__ __forceinline__ uint32_t f2h2(float lo, float hi) {
    __half2 h = __floats2half2_rn(lo, hi);
    return *reinterpret_cast<uint32_t*>(&h);
}

// D(16x8 f32) += A(16x16 f16) * B(16x8 f16)
__device__ __forceinline__ void mmaf16(float* c, const uint32_t* a, const uint32_t* b) {
    asm volatile(
        "mma.sync.aligned.m16n8k16.row.col.f32.f16.f16.f32 "
        "{%0,%1,%2,%3}, {%4,%5,%6,%7}, {%8,%9}, {%0,%1,%2,%3};\n"
        : "+f"(c[0]), "+f"(c[1]), "+f"(c[2]), "+f"(c[3])
        : "r"(a[0]), "r"(a[1]), "r"(a[2]), "r"(a[3]), "r"(b[0]), "r"(b[1]));
}

__device__ __forceinline__ void ldsm4(uint32_t* r, uint32_t addr) {
    asm volatile("ldmatrix.sync.aligned.m8n8.x4.shared.b16 {%0,%1,%2,%3}, [%4];"
                 : "=r"(r[0]), "=r"(r[1]), "=r"(r[2]), "=r"(r[3]) : "r"(addr));
}
__device__ __forceinline__ void ldsm2(uint32_t* r, uint32_t addr) {
    asm volatile("ldmatrix.sync.aligned.m8n8.x2.shared.b16 {%0,%1}, [%2];"
                 : "=r"(r[0]), "=r"(r[1]) : "r"(addr));
}

__device__ __forceinline__ void cp16(uint32_t dst, const void* src) {
    asm volatile("cp.async.cg.shared.global [%0], [%1], 16;\n" :: "r"(dst), "l"(src));
}
__device__ __forceinline__ void cp_commit() { asm volatile("cp.async.commit_group;\n"); }
__device__ __forceinline__ void cp_wait0() {
    asm volatile("cp.async.wait_group 0;\n" ::: "memory");
}

// exp(x) for x <= 0 on the FMA pipe (no MUFU). |rel err| ~ 2.4e-6.
__device__ __forceinline__ float fast_exp(float x) {
    x = fmaxf(x, -80.0f);
    float y = x * 1.4426950408889634f;
    float t = y + 12582912.0f;
    int   e = __float_as_int(t);
    float n = t - 12582912.0f;
    float f = y - n;
    float p = 1.3333558e-3f;
    p = fmaf(p, f, 9.6181291e-3f);
    p = fmaf(p, f, 5.5504109e-2f);
    p = fmaf(p, f, 2.4022651e-1f);
    p = fmaf(p, f, 6.9314718e-1f);
    p = fmaf(p, f, 1.0f);
    return __int_as_float(__float_as_int(p) + (e << 23));
}

// ---------------------------------------------------------------------------
// Kernel 0: round X + weights to fp16. X row-major; W stored transposed [n][k].
// ---------------------------------------------------------------------------
__global__ __launch_bounds__(256) void cvt_all(
    const float* __restrict__ X,  const float* __restrict__ Wq,
    const float* __restrict__ Wk, const float* __restrict__ Wv,
    const float* __restrict__ Wo)
{
    const int NX = MTOT * CHN / 4;
    const int NW = CHN * CHN / 4;
    int i = blockIdx.x * 256 + threadIdx.x;
    if (i < NX) {
        int base = i * 4;
        int row = base / CHN, c = base - row * CHN;
        float4 v = *(const float4*)&X[(size_t)row * CHN + c];
        uint2 u = make_uint2(f2h2(v.x, v.y), f2h2(v.z, v.w));
        *(uint2*)&g_xh[(size_t)row * CHN + c] = u;
        return;
    }
    i -= NX;
    if (i >= 4 * NW) return;
    const float* s; __half* d2;
    if (i < NW)          { s = Wq; d2 = g_wqh; }
    else if (i < 2 * NW) { s = Wk; d2 = g_wkh; i -= NW; }
    else if (i < 3 * NW) { s = Wv; d2 = g_wvh; i -= 2 * NW; }
    else                 { s = Wo; d2 = g_woh; i -= 3 * NW; }
    int base = i * 4;
    int k = base / CHN, n = base - k * CHN;
    float4 v = *(const float4*)&s[(size_t)k * CHN + n];
    d2[(size_t)(n + 0) * CHN + k] = __float2half_rn(v.x);
    d2[(size_t)(n + 1) * CHN + k] = __float2half_rn(v.y);
    d2[(size_t)(n + 2) * CHN + k] = __float2half_rn(v.z);
    d2[(size_t)(n + 3) * CHN + k] = __float2half_rn(v.w);
}

// ---------------------------------------------------------------------------
// fp16 GEMM core: CTA 128x128, 8 warps (2m x 4n), warp 64x32, k-chunks of 32.
// smem rows padded to 40 halfs (80B; 20 words mod 32 -> conflict-free).
// ---------------------------------------------------------------------------
__device__ __forceinline__ void hgemm_core(
    const __half* __restrict__ A, const __half* __restrict__ B,
    int row0, int col0, float c[16][4], __half* As, __half* Bs)
{
    uint32_t As_u = (uint32_t)__cvta_generic_to_shared(As);
    uint32_t Bs_u = (uint32_t)__cvta_generic_to_shared(Bs);

    const int tid = threadIdx.x;
    const int warp = tid >> 5, lane = tid & 31;
    const int wm = warp >> 2, wn = warp & 3;

    auto issue = [&](int kb, int buf) {
#pragma unroll
        for (int it = 0; it < 2; it++) {
            int lin = it * 256 + tid;             // 512: 128 rows x 4 segs
            int row = lin >> 2, seg = lin & 3;
            cp16(As_u + (uint32_t)(buf * 10240 + row * 80 + seg * 16),
                 &A[(size_t)(row0 + row) * CHN + kb + seg * 8]);
            cp16(Bs_u + (uint32_t)(buf * 10240 + row * 80 + seg * 16),
                 &B[(size_t)(col0 + row) * CHN + kb + seg * 8]);
        }
        cp_commit();
    };

    issue(0, 0);

    int buf = 0;
    for (int ic = 0; ic < 40; ic++, buf ^= 1) {
        cp_wait0();
        __syncthreads();
        if (ic + 1 < 40) issue((ic + 1) * 32, buf ^ 1);
#pragma unroll
        for (int ks = 0; ks < 2; ks++) {
            uint32_t af[4][4], bf[4][2];
#pragma unroll
            for (int mt = 0; mt < 4; mt++)
                ldsm4(af[mt], As_u + (uint32_t)(buf * 10240 +
                      (wm * 64 + mt * 16 + (lane & 15)) * 80 +
                      ks * 32 + (lane >> 4) * 16));
#pragma unroll
            for (int nt = 0; nt < 4; nt++)
                ldsm2(bf[nt], Bs_u + (uint32_t)(buf * 10240 +
                      (wn * 32 + nt * 8 + (lane & 7)) * 80 +
                      ks * 32 + ((lane >> 3) & 1) * 16));
#pragma unroll
            for (int mt = 0; mt < 4; mt++)
#pragma unroll
                for (int nt = 0; nt < 4; nt++)
                    mmaf16(c[mt * 4 + nt], af[mt], bf[nt]);
        }
    }
}

// ---------------------------------------------------------------------------
// Kernel 1: fused QKV projection (fp16 HMMA); epilogues write attn layouts.
// ---------------------------------------------------------------------------
__global__ __launch_bounds__(256, 2) void qkv_h()
{
    __shared__ __half As[2 * 128 * 40];
    __shared__ __half Bs[2 * 128 * 40];
    float c[16][4];
#pragma unroll
    for (int i = 0; i < 16; i++)
#pragma unroll
        for (int j = 0; j < 4; j++) c[i][j] = 0.f;

    const __half* __restrict__ W =
        (blockIdx.z == 0) ? g_wqh : (blockIdx.z == 1 ? g_wkh : g_wvh);
    hgemm_core(g_xh, W, blockIdx.y * 128, blockIdx.x * 128, c, As, Bs);

    const int lane = threadIdx.x & 31, warp = threadIdx.x >> 5;
    const int g = lane >> 2, t = lane & 3;
    const int wm = warp >> 2, wn = warp & 3;
    const float scale = 0.07905694150420949f;  // 1/sqrt(160)

#pragma unroll
    for (int mt = 0; mt < 4; mt++) {
#pragma unroll
        for (int nt = 0; nt < 4; nt++) {
            int r = blockIdx.y * 128 + wm * 64 + mt * 16 + g;
            int col = blockIdx.x * 128 + wn * 32 + nt * 8 + 2 * t;
            int h = col / HDIM, d = col - h * HDIM;
            float* cc = c[mt * 4 + nt];
            if (blockIdx.z == 0) {
#pragma unroll
                for (int hf = 0; hf < 2; hf++) {
                    int row = r + hf * 8;
                    int b = row >> 12, s = row & (SEQ - 1);
                    size_t o = ((size_t)(b * HEADS + h) * SEQ + s) * HDIM + d;
                    *(uint32_t*)&g_qh[o] = f2h2(cc[hf * 2] * scale, cc[hf * 2 + 1] * scale);
                }
            } else if (blockIdx.z == 1) {
#pragma unroll
                for (int hf = 0; hf < 2; hf++) {
                    int row = r + hf * 8;
                    int b = row >> 12, s = row & (SEQ - 1);
                    size_t o = ((size_t)(b * HEADS + h) * SEQ + s) * HDIM + d;
                    *(uint32_t*)&g_kh[o] = f2h2(cc[hf * 2], cc[hf * 2 + 1]);
                }
            } else {
#pragma unroll
                for (int i = 0; i < 4; i++) {
                    int row = r + (i >> 1) * 8;
                    int b = row >> 12, s = row & (SEQ - 1);
                    g_vh[((size_t)(b * HEADS + h) * HDIM + d + (i & 1)) * SEQ + s] =
                        __float2half_rn(cc[i]);
                }
            }
        }
    }
}

// ---------------------------------------------------------------------------
// Kernel 2: flash attention, fp16 HMMA. CTA: 128 q rows, 8 warps x 16 q rows.
// KV tile = 32 keys; each warp owns the full key width -> warp-local softmax,
// P flows from S accum regs directly into PV A-frags (no smem, no shuffles).
// ---------------------------------------------------------------------------
__global__ __launch_bounds__(256, 1) void attn_h()
{
    __shared__ __half sK[2][32][168];   // [buf][key][d pad 168]
    __shared__ __half sV[2][160][40];   // [buf][d][key pad 40]

    const int bh = blockIdx.y;
    const int q0 = blockIdx.x * 128;
    const int tid = threadIdx.x, w = tid >> 5, lane = tid & 31;
    const int g = lane >> 2, t = lane & 3;
    const int r0 = q0 + w * 16 + g;              // this thread's first q row

    // ---- Q fragments straight from gmem (pre-scaled fp16) ----
    uint32_t qa[10][4];
    {
        const __half* Qb = &g_qh[((size_t)bh * SEQ + r0) * HDIM];
#pragma unroll
        for (int ks = 0; ks < 10; ks++) {
            qa[ks][0] = *(const uint32_t*)(Qb + ks * 16 + 2 * t);
            qa[ks][1] = *(const uint32_t*)(Qb + 8 * HDIM + ks * 16 + 2 * t);
            qa[ks][2] = *(const uint32_t*)(Qb + ks * 16 + 8 + 2 * t);
            qa[ks][3] = *(const uint32_t*)(Qb + 8 * HDIM + ks * 16 + 8 + 2 * t);
        }
    }

    uint32_t sK_u = (uint32_t)__cvta_generic_to_shared(&sK[0][0][0]);
    uint32_t sV_u = (uint32_t)__cvta_generic_to_shared(&sV[0][0][0]);
    const __half* __restrict__ Kg = &g_kh[(size_t)bh * SEQ * HDIM];
    const __half* __restrict__ Vg = &g_vh[(size_t)bh * HDIM * SEQ];

    auto issue = [&](int kt, int buf) {
#pragma unroll
        for (int it = 0; it < 5; it++) {
            int lin = it * 256 + tid;            // 1280 cp16 total
            if (lin < 640) {                     // K: 32 rows x 20 segs
                int row = lin / 20, seg = lin - row * 20;
                cp16(sK_u + (uint32_t)(buf * 10752 + row * 336 + seg * 16),
                     Kg + (size_t)(kt + row) * HDIM + seg * 8);
            } else {                             // V: 160 rows x 4 segs
                int v = lin - 640;
                int d = v >> 2, seg = v & 3;
                cp16(sV_u + (uint32_t)(buf * 12800 + d * 80 + seg * 16),
                     Vg + (size_t)d * SEQ + kt + seg * 8);
            }
        }
        cp_commit();
    };
    issue(0, 0);

    float o[20][4];
#pragma unroll
    for (int nt = 0; nt < 20; nt++)
#pragma unroll
        for (int j = 0; j < 4; j++) o[nt][j] = 0.f;
    float m0 = -1e30f, m1 = -1e30f, l0 = 0.f, l1 = 0.f;

    for (int it = 0; it < 128; it++) {
        const int buf = it & 1;
        cp_wait0();
        __syncthreads();                 // tile arrived + everyone done with buf^1
        if (it + 1 < 128) issue((it + 1) * 32, buf ^ 1);

        // ---- S = Q @ K^T (16q x 32k per warp, full tile width) ----
        float s[4][4];
#pragma unroll
        for (int nt = 0; nt < 4; nt++)
#pragma unroll
            for (int j = 0; j < 4; j++) s[nt][j] = 0.f;
#pragma unroll
        for (int ks = 0; ks < 10; ks++) {
#pragma unroll
            for (int nt = 0; nt < 4; nt++) {
                uint32_t kb[2];
                ldsm2(kb, sK_u + (uint32_t)(buf * 10752 +
                      (nt * 8 + (lane & 7)) * 336 +
                      ks * 32 + ((lane >> 3) & 1) * 16));
                mmaf16(s[nt], qa[ks], kb);
            }
        }

        // ---- warp-local online softmax (rows g and g+8) ----
        float mx0 = fmaxf(fmaxf(s[0][0], s[0][1]), fmaxf(s[1][0], s[1][1]));
        mx0 = fmaxf(mx0, fmaxf(fmaxf(s[2][0], s[2][1]), fmaxf(s[3][0], s[3][1])));
        float mx1 = fmaxf(fmaxf(s[0][2], s[0][3]), fmaxf(s[1][2], s[1][3]));
        mx1 = fmaxf(mx1, fmaxf(fmaxf(s[2][2], s[2][3]), fmaxf(s[3][2], s[3][3])));
        mx0 = fmaxf(mx0, __shfl_xor_sync(0xffffffffu, mx0, 1));
        mx0 = fmaxf(mx0, __shfl_xor_sync(0xffffffffu, mx0, 2));
        mx1 = fmaxf(mx1, __shfl_xor_sync(0xffffffffu, mx1, 1));
        mx1 = fmaxf(mx1, __shfl_xor_sync(0xffffffffu, mx1, 2));

        float mn0 = fmaxf(m0, mx0), mn1 = fmaxf(m1, mx1);
        float a0 = fast_exp(m0 - mn0), a1 = fast_exp(m1 - mn1);
        m0 = mn0; m1 = mn1;

        float p[4][4];
        float sum0 = 0.f, sum1 = 0.f;
#pragma unroll
        for (int nt = 0; nt < 4; nt++) {
            p[nt][0] = fast_exp(s[nt][0] - mn0);
            p[nt][1] = fast_exp(s[nt][1] - mn0);
            p[nt][2] = fast_exp(s[nt][2] - mn1);
            p[nt][3] = fast_exp(s[nt][3] - mn1);
            sum0 += p[nt][0] + p[nt][1];
            sum1 += p[nt][2] + p[nt][3];
        }
        sum0 += __shfl_xor_sync(0xffffffffu, sum0, 1);
        sum0 += __shfl_xor_sync(0xffffffffu, sum0, 2);
        sum1 += __shfl_xor_sync(0xffffffffu, sum1, 1);
        sum1 += __shfl_xor_sync(0xffffffffu, sum1, 2);
        l0 = l0 * a0 + sum0;
        l1 = l1 * a1 + sum1;

        // ---- P accum regs -> fp16 A-frags (layout matches exactly) ----
        uint32_t pa[2][4];
#pragma unroll
        for (int j2 = 0; j2 < 2; j2++) {
            pa[j2][0] = f2h2(p[2 * j2][0],     p[2 * j2][1]);
            pa[j2][1] = f2h2(p[2 * j2][2],     p[2 * j2][3]);
            pa[j2][2] = f2h2(p[2 * j2 + 1][0], p[2 * j2 + 1][1]);
            pa[j2][3] = f2h2(p[2 * j2 + 1][2], p[2 * j2 + 1][3]);
        }

        // ---- rescale O, then O += P @ V ----
#pragma unroll
        for (int nt = 0; nt < 20; nt++) {
            o[nt][0] *= a0; o[nt][1] *= a0;
            o[nt][2] *= a1; o[nt][3] *= a1;
        }
#pragma unroll
        for (int j2 = 0; j2 < 2; j2++) {
#pragma unroll
            for (int nt = 0; nt < 20; nt++) {
                uint32_t vb[2];
                ldsm2(vb, sV_u + (uint32_t)(buf * 12800 +
                      (nt * 8 + (lane & 7)) * 80 +
                      j2 * 32 + ((lane >> 3) & 1) * 16));
                mmaf16(o[nt], pa[j2], vb);
            }
        }
    }

    // ---- epilogue: O / l -> g_aoh [row][1280] fp16 ----
    const int b = bh >> 3, h = bh & 7;
    float inv0 = 1.0f / l0, inv1 = 1.0f / l1;
    size_t ro0 = (size_t)(b * SEQ + r0) * CHN + h * HDIM;
    size_t ro1 = (size_t)(b * SEQ + r0 + 8) * CHN + h * HDIM;
#pragma unroll
    for (int nt = 0; nt < 20; nt++) {
        int d = nt * 8 + 2 * t;
        *(uint32_t*)&g_aoh[ro0 + d] = f2h2(o[nt][0] * inv0, o[nt][1] * inv0);
        *(uint32_t*)&g_aoh[ro1 + d] = f2h2(o[nt][2] * inv1, o[nt][3] * inv1);
    }
}

// ---------------------------------------------------------------------------
// Kernel 3: output projection + bias (fp16 HMMA, f32 out)
// ---------------------------------------------------------------------------
__global__ __launch_bounds__(256, 2) void out_h(
    const float* __restrict__ bias, float* __restrict__ out)
{
    __shared__ __half As[2 * 128 * 40];
    __shared__ __half Bs[2 * 128 * 40];
    float c[16][4];
#pragma unroll
    for (int i = 0; i < 16; i++)
#pragma unroll
        for (int j = 0; j < 4; j++) c[i][j] = 0.f;

    hgemm_core(g_aoh, g_woh, blockIdx.y * 128, blockIdx.x * 128, c, As, Bs);

    const int lane = threadIdx.x & 31, warp = threadIdx.x >> 5;
    const int g = lane >> 2, t = lane & 3;
    const int wm = warp >> 2, wn = warp & 3;

#pragma unroll
    for (int mt = 0; mt < 4; mt++) {
#pragma unroll
        for (int nt = 0; nt < 4; nt++) {
            int r = blockIdx.y * 128 + wm * 64 + mt * 16 + g;
            int col = blockIdx.x * 128 + wn * 32 + nt * 8 + 2 * t;
            float2 bv = *(const float2*)&bias[col];
            float* cc = c[mt * 4 + nt];
#pragma unroll
            for (int hf = 0; hf < 2; hf++) {
                int row = r + hf * 8;
                *(float2*)&out[(size_t)row * CHN + col] =
                    make_float2(cc[hf * 2] + bv.x, cc[hf * 2 + 1] + bv.y);
            }
        }
    }
}

// ---------------------------------------------------------------------------
extern "C" void kernel_launch(void* const* d_in, const int* in_sizes, int n_in,
                              void* d_out, int out_size)
{
    const float* X    = (const float*)d_in[0];
    const float* Wq   = (const float*)d_in[1];
    const float* Wk   = (const float*)d_in[2];
    const float* Wv   = (const float*)d_in[3];
    const float* Wout = (const float*)d_in[4];
    const float* bout = (const float*)d_in[5];
    float* out = (float*)d_out;

    const int NX = MTOT * CHN / 4, NW = CHN * CHN / 4;
    cvt_all<<<(NX + 4 * NW + 255) / 256, 256>>>(X, Wq, Wk, Wv, Wout);

    qkv_h<<<dim3(CHN / 128, MTOT / 128, 3), 256>>>();

    attn_h<<<dim3(SEQ / 128, BHN), 256>>>();

    out_h<<<dim3(CHN / 128, MTOT / 128), 256>>>(bout, out);
}